// round 7
// baseline (speedup 1.0000x reference)
#include <cuda_runtime.h>
#include <cuda_bf16.h>
#include <cstdint>
#include <cfloat>

// Problem constants
#define NPTS 32768   // candidate points per side
#define MQ   8192    // query (shortcut) points per side
#define CF   256     // feature channels

// Grid constants
#define G     64
#define G3    (G * G * G)          // 262144 cells per side
#define HCELL 0.125f
#define INVH  8.0f
#define ORI   (-4.0f)
#define CAP   16                   // points per bin
#define OVMAX 4096                 // overflow list capacity per side
#define RBOX  2                    // phase-1 box radius (5x5x5 = 125 cells)

// Radius-band constants (phase 2)
#define NRB    256
#define RBW    0.025f
#define INVRBW 40.0f

// ---------------- scratch ----------------
__device__ int    g_cnt[2 * G3];                 // per-cell counts (2 MB)
__device__ float4 g_bin[2 * G3 * CAP];           // binned points (134 MB)
__device__ int    g_ovn[2];                      // overflow counts
__device__ float4 g_ov[2][OVMAX];                // overflow points
__device__ int    g_rcnt[2][NRB];                // radius-bin histogram
__device__ int    g_roff[2][NRB + 1];            // radius-bin offsets
__device__ int    g_rcur[2][NRB];                // radius scatter cursor
__device__ float4 g_pts_r[2][NPTS];              // radius-sorted points
__device__ int    g_failn;                       // unresolved query count
__device__ int    g_fail[2 * MQ];                // unresolved (side<<16 | q)
__device__ float  g_faild2[2 * MQ];              // phase-1 d2 upper bound

// ---------------- helpers ----------------
__device__ __forceinline__ int cell_of(float v) {
    int c = (int)floorf((v - ORI) * INVH);
    return min(max(c, 0), G - 1);
}

__device__ __forceinline__ int rbin_of(float rho) {
    int b = (int)(rho * INVRBW);
    return min(b, NRB - 1);
}

struct Top2 {
    float d1, d2;
    int   i1, i2;
};

__device__ __forceinline__ void t2_ins(Top2& t, float d, int j) {
    bool a = d < t.d1;
    bool b = d < t.d2;
    t.i2 = a ? t.i1 : (b ? j : t.i2);
    t.d2 = a ? t.d1 : (b ? d : t.d2);
    t.i1 = a ? j : t.i1;
    t.d1 = a ? d : t.d1;
}

__device__ __forceinline__ void t2_merge(Top2& a, const Top2& b) {
    t2_ins(a, b.d1, b.i1);
    t2_ins(a, b.d2, b.i2);
}

__device__ __forceinline__ Top2 warp_merge(Top2 t) {
    #pragma unroll
    for (int off = 16; off; off >>= 1) {
        float od1 = __shfl_xor_sync(0xffffffffu, t.d1, off);
        int   oi1 = __shfl_xor_sync(0xffffffffu, t.i1, off);
        float od2 = __shfl_xor_sync(0xffffffffu, t.d2, off);
        int   oi2 = __shfl_xor_sync(0xffffffffu, t.i2, off);
        t2_ins(t, od1, oi1);
        t2_ins(t, od2, oi2);
    }
    return t;
}

// ---------------- K0: zero counts ----------------
__global__ void zero_kernel() {
    int gid = blockIdx.x * blockDim.x + threadIdx.x;
    if (gid < 2 * G3) g_cnt[gid] = 0;
    if (gid < 2 * NRB) ((int*)g_rcnt)[gid] = 0;
    if (gid < 2) g_ovn[gid] = 0;
    if (gid == 0) g_failn = 0;
}

// ---------------- K1: scatter into cell bins + radius histogram ----------------
__global__ void scatter_kernel(const float* __restrict__ src_coords,
                               const float* __restrict__ tgt_coords) {
    int u = blockIdx.x * blockDim.x + threadIdx.x;
    if (u >= 2 * NPTS) return;
    int side = u >> 15;
    int i = u & (NPTS - 1);
    const float* c = side ? tgt_coords : src_coords;
    float x = c[3 * i], y = c[3 * i + 1], z = c[3 * i + 2];
    int cell = side * G3 + (cell_of(z) * G + cell_of(y)) * G + cell_of(x);
    float4 p = make_float4(x, y, z, __int_as_float(i));
    int slot = atomicAdd(&g_cnt[cell], 1);
    if (slot < CAP) {
        g_bin[cell * CAP + slot] = p;
    } else {
        int o = atomicAdd(&g_ovn[side], 1);
        if (o < OVMAX) g_ov[side][o] = p;
    }
    float rho = sqrtf(fmaf(x, x, fmaf(y, y, z * z)));
    atomicAdd(&g_rcnt[side][rbin_of(rho)], 1);
}

// ---------------- K1b: scan radius histogram (1 block, 512 thr) ----------------
__global__ void rscan_kernel() {
    __shared__ int sh[2][NRB];
    int side = threadIdx.x >> 8;
    int b = threadIdx.x & (NRB - 1);
    sh[side][b] = g_rcnt[side][b];
    __syncthreads();
    #pragma unroll
    for (int off = 1; off < NRB; off <<= 1) {
        int v = (b >= off) ? sh[side][b - off] : 0;
        __syncthreads();
        sh[side][b] += v;
        __syncthreads();
    }
    g_roff[side][b + 1] = sh[side][b];
    int excl = (b == 0) ? 0 : sh[side][b - 1];
    if (b == 0) g_roff[side][0] = 0;
    g_rcur[side][b] = excl;
}

// ---------------- K1c: scatter into radius-sorted array ----------------
__global__ void rscatter_kernel(const float* __restrict__ src_coords,
                                const float* __restrict__ tgt_coords) {
    int u = blockIdx.x * blockDim.x + threadIdx.x;
    if (u >= 2 * NPTS) return;
    int side = u >> 15;
    int i = u & (NPTS - 1);
    const float* c = side ? tgt_coords : src_coords;
    float x = c[3 * i], y = c[3 * i + 1], z = c[3 * i + 2];
    float rho = sqrtf(fmaf(x, x, fmaf(y, y, z * z)));
    int pos = atomicAdd(&g_rcur[side][rbin_of(rho)], 1);
    g_pts_r[side][pos] = make_float4(x, y, z, __int_as_float(i));
}

// ---------------- K2: phase-1 warp-per-query + fused gather ----------------
__global__ __launch_bounds__(256)
void search1_kernel(const float* __restrict__ src_sc,
                    const float* __restrict__ tgt_sc,
                    const float* __restrict__ src_feat,
                    const float* __restrict__ tgt_feat,
                    float* __restrict__ out) {
    int wid = (blockIdx.x * blockDim.x + threadIdx.x) >> 5;
    int lane = threadIdx.x & 31;
    if (wid >= 2 * MQ) return;
    int side = wid >> 13;
    int q = wid & (MQ - 1);
    const float* sc = side ? tgt_sc : src_sc;
    float qx = sc[3 * q], qy = sc[3 * q + 1], qz = sc[3 * q + 2];
    int cx = cell_of(qx), cy = cell_of(qy), cz = cell_of(qz);
    int sbase = side * G3;

    Top2 t;
    t.d1 = FLT_MAX; t.d2 = FLT_MAX; t.i1 = -1; t.i2 = -1;

    const int S = 2 * RBOX + 1;            // 5
    const int TOT = S * S * S;             // 125
    for (int c = lane; c < TOT; c += 32) {
        int dz = c / (S * S);
        int rem = c - dz * (S * S);
        int dy = rem / S;
        int dx = rem - dy * S;
        int x = cx + dx - RBOX, y = cy + dy - RBOX, z = cz + dz - RBOX;
        if ((unsigned)x >= G || (unsigned)y >= G || (unsigned)z >= G) continue;
        int cell = sbase + (z * G + y) * G + x;
        int n = min(g_cnt[cell], CAP);
        int base = cell * CAP;
        for (int k = 0; k < n; k++) {
            float4 p = g_bin[base + k];
            float ddx = qx - p.x, ddy = qy - p.y, ddz = qz - p.z;
            float d = fmaf(ddx, ddx, fmaf(ddy, ddy, ddz * ddz));
            t2_ins(t, d, __float_as_int(p.w));
        }
    }
    // overflow points (never duplicated in bins)
    int ovn = min(g_ovn[side], OVMAX);
    for (int o = lane; o < ovn; o += 32) {
        float4 p = g_ov[side][o];
        float ddx = qx - p.x, ddy = qy - p.y, ddz = qz - p.z;
        float d = fmaf(ddx, ddx, fmaf(ddy, ddy, ddz * ddz));
        t2_ins(t, d, __float_as_int(p.w));
    }

    Top2 m = warp_merge(t);
    const float bnd2 = (RBOX * HCELL) * (RBOX * HCELL);   // 0.0625
    if (m.d2 <= bnd2) {
        // fused gather: warp copies the 1 KB feature row
        const float* f = side ? tgt_feat : src_feat;
        const float4* srcp = (const float4*)(f + (size_t)m.i2 * CF);
        float4* dstp = (float4*)(out + (size_t)(side * MQ + q) * CF);
        dstp[lane]      = __ldg(&srcp[lane]);
        dstp[lane + 32] = __ldg(&srcp[lane + 32]);
    } else if (lane == 0) {
        int o = atomicAdd(&g_failn, 1);
        g_fail[o] = (side << 16) | q;
        g_faild2[o] = m.d2;
    }
}

// ---------------- K3: phase-2 radius-banded brute force + fused gather ----------------
__global__ __launch_bounds__(256)
void search2_kernel(const float* __restrict__ src_sc,
                    const float* __restrict__ tgt_sc,
                    const float* __restrict__ src_feat,
                    const float* __restrict__ tgt_feat,
                    float* __restrict__ out) {
    __shared__ Top2 part[8];
    __shared__ int res_i2;
    int tid = threadIdx.x;
    int warp = tid >> 5;
    int lane = tid & 31;
    int nf = g_failn;

    for (int item = blockIdx.x; item < nf; item += gridDim.x) {
        int packed = g_fail[item];
        float d2cap = g_faild2[item];
        int side = packed >> 16;
        int q = packed & 0xffff;
        const float* sc = side ? tgt_sc : src_sc;
        float qx = sc[3 * q], qy = sc[3 * q + 1], qz = sc[3 * q + 2];
        float rq = sqrtf(fmaf(qx, qx, fmaf(qy, qy, qz * qz)));

        int lo, hi;
        if (d2cap < FLT_MAX) {
            float D = sqrtf(d2cap);
            int blo = max((int)((rq - D) * INVRBW), 0);
            int bhi = min((int)((rq + D) * INVRBW) + 1, NRB - 1);
            lo = g_roff[side][blo];
            hi = g_roff[side][bhi + 1];
        } else {
            lo = 0; hi = NPTS;          // rare: no bound -> full scan
        }
        const float4* pts = g_pts_r[side];

        Top2 t0, t1;
        t0.d1 = FLT_MAX; t0.d2 = FLT_MAX; t0.i1 = -1; t0.i2 = -1;
        t1 = t0;

        for (int base = lo + tid; base < hi; base += 512) {
            float4 p0 = __ldg(&pts[base]);
            float dx0 = qx - p0.x, dy0 = qy - p0.y, dz0 = qz - p0.z;
            float d0 = fmaf(dx0, dx0, fmaf(dy0, dy0, dz0 * dz0));
            t2_ins(t0, d0, __float_as_int(p0.w));
            int i1 = base + 256;
            if (i1 < hi) {
                float4 p1 = __ldg(&pts[i1]);
                float dx1 = qx - p1.x, dy1 = qy - p1.y, dz1 = qz - p1.z;
                float d1 = fmaf(dx1, dx1, fmaf(dy1, dy1, dz1 * dz1));
                t2_ins(t1, d1, __float_as_int(p1.w));
            }
        }
        t2_merge(t0, t1);

        Top2 w = warp_merge(t0);
        if (lane == 0) part[warp] = w;
        __syncthreads();
        if (tid == 0) {
            Top2 m = part[0];
            #pragma unroll
            for (int s = 1; s < 8; s++) t2_merge(m, part[s]);
            res_i2 = m.i2;
        }
        __syncthreads();
        int idx = res_i2;

        // fused gather: 256 threads copy 256 floats (1 KB row)
        const float* f = side ? tgt_feat : src_feat;
        out[(size_t)(side * MQ + q) * CF + tid] = __ldg(&f[(size_t)idx * CF + tid]);
        __syncthreads();
    }
}

extern "C" void kernel_launch(void* const* d_in, const int* in_sizes, int n_in,
                              void* d_out, int out_size) {
    const float* src        = (const float*)d_in[0];   // [N, C]
    const float* tgt        = (const float*)d_in[1];   // [N, C]
    const float* src_coords = (const float*)d_in[2];   // [N, 3]
    const float* tgt_coords = (const float*)d_in[3];   // [N, 3]
    const float* src_sc     = (const float*)d_in[4];   // [M, 3]
    const float* tgt_sc     = (const float*)d_in[5];   // [M, 3]
    float* out = (float*)d_out;                        // [2*M, C]

    zero_kernel<<<(2 * G3 + 255) / 256, 256>>>();
    scatter_kernel<<<(2 * NPTS + 255) / 256, 256>>>(src_coords, tgt_coords);
    rscan_kernel<<<1, 512>>>();
    rscatter_kernel<<<(2 * NPTS + 255) / 256, 256>>>(src_coords, tgt_coords);
    search1_kernel<<<(2 * MQ * 32 + 255) / 256, 256>>>(src_sc, tgt_sc, src, tgt, out);
    search2_kernel<<<2048, 256>>>(src_sc, tgt_sc, src, tgt, out);
}

// round 10
// speedup vs baseline: 1.2153x; 1.2153x over previous
#include <cuda_runtime.h>
#include <cuda_bf16.h>
#include <cstdint>
#include <cfloat>

// Problem constants
#define NPTS 32768   // candidate points per side
#define MQ   8192    // query (shortcut) points per side
#define CF   256     // feature channels

// Grid constants
#define G     64
#define G3    (G * G * G)          // 262144 cells per side
#define HCELL 0.125f
#define INVH  8.0f
#define ORI   (-4.0f)
#define CAP   16                   // points per cell bin
#define OVMAX 4096                 // cell overflow list capacity per side
#define RBOX  2                    // phase-1 box radius (5x5x5 = 125 cells)

// Radius-band constants (phase 2)
#define NRB     64
#define RBWF    0.1f
#define INVRBW  10.0f
#define RCAP    2560               // points per radius bin
#define ROVMAX  2048               // radius spill capacity per side

// ---------------- scratch ----------------
__device__ int    g_cnt[2 * G3];                 // per-cell counts (2 MB)
__device__ float4 g_bin[2 * G3 * CAP];           // cell-binned points (134 MB)
__device__ int    g_ovn[2];                      // cell overflow counts
__device__ float4 g_ov[2][OVMAX];                // cell overflow points
__device__ int    g_rcnt[2][NRB];                // radius-bin counts
__device__ float4 g_rbin[2][NRB][RCAP];          // radius-binned points (5.2 MB)
__device__ int    g_rovn[2];                     // radius spill counts
__device__ float4 g_rov[2][ROVMAX];              // radius spill points
__device__ int    g_idx2[2][MQ];                 // 2nd-NN index per query
__device__ int    g_failn;                       // unresolved query count
__device__ int    g_fail[2 * MQ];                // unresolved (side<<16 | q)

// ---------------- helpers ----------------
__device__ __forceinline__ int cell_of(float v) {
    int c = (int)floorf((v - ORI) * INVH);
    return min(max(c, 0), G - 1);
}

__device__ __forceinline__ int rbin_of(float rho) {
    int b = (int)(rho * INVRBW);
    return min(b, NRB - 1);
}

struct Top2 {
    float d1, d2;
    int   i1, i2;
};

__device__ __forceinline__ void t2_ins(Top2& t, float d, int j) {
    bool a = d < t.d1;
    bool b = d < t.d2;
    t.i2 = a ? t.i1 : (b ? j : t.i2);
    t.d2 = a ? t.d1 : (b ? d : t.d2);
    t.i1 = a ? j : t.i1;
    t.d1 = a ? d : t.d1;
}

__device__ __forceinline__ void t2_merge(Top2& a, const Top2& b) {
    t2_ins(a, b.d1, b.i1);
    t2_ins(a, b.d2, b.i2);
}

__device__ __forceinline__ Top2 warp_merge(Top2 t) {
    #pragma unroll
    for (int off = 16; off; off >>= 1) {
        float od1 = __shfl_xor_sync(0xffffffffu, t.d1, off);
        int   oi1 = __shfl_xor_sync(0xffffffffu, t.i1, off);
        float od2 = __shfl_xor_sync(0xffffffffu, t.d2, off);
        int   oi2 = __shfl_xor_sync(0xffffffffu, t.i2, off);
        t2_ins(t, od1, oi1);
        t2_ins(t, od2, oi2);
    }
    return t;
}

// ---------------- K0: zero counts ----------------
__global__ void zero_kernel() {
    int gid = blockIdx.x * blockDim.x + threadIdx.x;
    if (gid < 2 * G3) g_cnt[gid] = 0;
    if (gid < 2 * NRB) ((int*)g_rcnt)[gid] = 0;
    if (gid < 2) { g_ovn[gid] = 0; g_rovn[gid] = 0; }
    if (gid == 0) g_failn = 0;
}

// ---------------- K1: scatter into cell bins + radius bins ----------------
__global__ void scatter_kernel(const float* __restrict__ src_coords,
                               const float* __restrict__ tgt_coords) {
    int u = blockIdx.x * blockDim.x + threadIdx.x;
    if (u >= 2 * NPTS) return;
    int side = u >> 15;
    int i = u & (NPTS - 1);
    const float* c = side ? tgt_coords : src_coords;
    float x = c[3 * i], y = c[3 * i + 1], z = c[3 * i + 2];
    float4 p = make_float4(x, y, z, __int_as_float(i));

    // cell bin (phase 1)
    int cell = side * G3 + (cell_of(z) * G + cell_of(y)) * G + cell_of(x);
    int slot = atomicAdd(&g_cnt[cell], 1);
    if (slot < CAP) {
        g_bin[cell * CAP + slot] = p;
    } else {
        int o = atomicAdd(&g_ovn[side], 1);
        if (o < OVMAX) g_ov[side][o] = p;
    }

    // radius bin (phase 2)
    float rho = sqrtf(fmaf(x, x, fmaf(y, y, z * z)));
    int rb = rbin_of(rho);
    int rs = atomicAdd(&g_rcnt[side][rb], 1);
    if (rs < RCAP) {
        g_rbin[side][rb][rs] = p;
    } else {
        int o = atomicAdd(&g_rovn[side], 1);
        if (o < ROVMAX) g_rov[side][o] = p;
    }
}

// ---------------- K2: phase-1 warp-per-query, fixed r=2 box ----------------
__global__ __launch_bounds__(256)
void search1_kernel(const float* __restrict__ src_sc,
                    const float* __restrict__ tgt_sc) {
    int wid = (blockIdx.x * blockDim.x + threadIdx.x) >> 5;
    int lane = threadIdx.x & 31;
    if (wid >= 2 * MQ) return;
    int side = wid >> 13;
    int q = wid & (MQ - 1);
    const float* sc = side ? tgt_sc : src_sc;
    float qx = sc[3 * q], qy = sc[3 * q + 1], qz = sc[3 * q + 2];
    int cx = cell_of(qx), cy = cell_of(qy), cz = cell_of(qz);
    int sbase = side * G3;

    Top2 t;
    t.d1 = FLT_MAX; t.d2 = FLT_MAX; t.i1 = -1; t.i2 = -1;

    const int S = 2 * RBOX + 1;            // 5
    const int TOT = S * S * S;             // 125
    for (int c = lane; c < TOT; c += 32) {
        int dz = c / (S * S);
        int rem = c - dz * (S * S);
        int dy = rem / S;
        int dx = rem - dy * S;
        int x = cx + dx - RBOX, y = cy + dy - RBOX, z = cz + dz - RBOX;
        if ((unsigned)x >= G || (unsigned)y >= G || (unsigned)z >= G) continue;
        int cell = sbase + (z * G + y) * G + x;
        int n = min(g_cnt[cell], CAP);
        int base = cell * CAP;
        for (int k = 0; k < n; k++) {
            float4 p = g_bin[base + k];
            float ddx = qx - p.x, ddy = qy - p.y, ddz = qz - p.z;
            float d = fmaf(ddx, ddx, fmaf(ddy, ddy, ddz * ddz));
            t2_ins(t, d, __float_as_int(p.w));
        }
    }
    // cell overflow points (never duplicated in bins)
    int ovn = min(g_ovn[side], OVMAX);
    for (int o = lane; o < ovn; o += 32) {
        float4 p = g_ov[side][o];
        float ddx = qx - p.x, ddy = qy - p.y, ddz = qz - p.z;
        float d = fmaf(ddx, ddx, fmaf(ddy, ddy, ddz * ddz));
        t2_ins(t, d, __float_as_int(p.w));
    }

    Top2 m = warp_merge(t);
    const float bnd2 = (RBOX * HCELL) * (RBOX * HCELL);   // 0.0625
    if (m.d2 <= bnd2) {
        if (lane == 0) g_idx2[side][q] = m.i2;
    } else if (lane == 0) {
        int o = atomicAdd(&g_failn, 1);
        g_fail[o] = (side << 16) | q;
    }
}

// ---------------- K3: phase-2 expanding radial-window scan ----------------
// Block-per-item. Scan the query's radius bin, then repeatedly scan the
// nearest unscanned bin; stop when both window edges certify (gap^2 >= d2).
// Lower bound: dist(q,p) >= |rho_p - rho_q|  (reverse triangle inequality).
__global__ __launch_bounds__(256)
void search2_kernel(const float* __restrict__ src_sc,
                    const float* __restrict__ tgt_sc) {
    __shared__ Top2 part[8];
    __shared__ int s_dir;
    int tid = threadIdx.x;
    int warp = tid >> 5;
    int lane = tid & 31;
    int nf = g_failn;

    for (int item = blockIdx.x; item < nf; item += gridDim.x) {
        int packed = g_fail[item];
        int side = packed >> 16;
        int q = packed & 0xffff;
        const float* sc = side ? tgt_sc : src_sc;
        float qx = sc[3 * q], qy = sc[3 * q + 1], qz = sc[3 * q + 2];
        float rq = sqrtf(fmaf(qx, qx, fmaf(qy, qy, qz * qz)));

        Top2 t;
        t.d1 = FLT_MAX; t.d2 = FLT_MAX; t.i1 = -1; t.i2 = -1;

        // radius spill points (disjoint from radius bins)
        int rovn = min(g_rovn[side], ROVMAX);
        for (int o = tid; o < rovn; o += 256) {
            float4 p = g_rov[side][o];
            float ddx = qx - p.x, ddy = qy - p.y, ddz = qz - p.z;
            float d = fmaf(ddx, ddx, fmaf(ddy, ddy, ddz * ddz));
            t2_ins(t, d, __float_as_int(p.w));
        }

        int b0 = rbin_of(rq);
        int lo = b0, hi = b0;

        // scan initial bin
        {
            int n = min(g_rcnt[side][b0], RCAP);
            const float4* bin = g_rbin[side][b0];
            for (int i = tid; i < n; i += 256) {
                float4 p = __ldg(&bin[i]);
                float ddx = qx - p.x, ddy = qy - p.y, ddz = qz - p.z;
                float d = fmaf(ddx, ddx, fmaf(ddy, ddy, ddz * ddz));
                t2_ins(t, d, __float_as_int(p.w));
            }
        }

        for (;;) {
            // block reduce current partials
            Top2 w = warp_merge(t);
            if (lane == 0) part[warp] = w;
            __syncthreads();
            if (tid == 0) {
                Top2 m = part[0];
                #pragma unroll
                for (int s = 1; s < 8; s++) t2_merge(m, part[s]);
                float gapLo = rq - (float)lo * RBWF;          // to lower edge
                float gapHi = (float)(hi + 1) * RBWF - rq;    // to upper edge
                bool loOpen = (lo > 0) && (gapLo * gapLo < m.d2);
                bool hiOpen = (hi < NRB - 1) && (gapHi * gapHi < m.d2);
                int dir = 0;
                if (loOpen && (!hiOpen || gapLo <= gapHi)) dir = -1;
                else if (hiOpen) dir = 1;
                s_dir = dir;
                if (dir == 0) g_idx2[side][q] = m.i2;
            }
            __syncthreads();
            int dir = s_dir;
            if (dir == 0) break;
            int b = (dir < 0) ? (lo - 1) : (hi + 1);
            if (dir < 0) lo = b; else hi = b;
            int n = min(g_rcnt[side][b], RCAP);
            const float4* bin = g_rbin[side][b];
            for (int i = tid; i < n; i += 256) {
                float4 p = __ldg(&bin[i]);
                float ddx = qx - p.x, ddy = qy - p.y, ddz = qz - p.z;
                float d = fmaf(ddx, ddx, fmaf(ddy, ddy, ddz * ddz));
                t2_ins(t, d, __float_as_int(p.w));
            }
            __syncthreads();
        }
        __syncthreads();
    }
}

// ---------------- K4: gather features ----------------
// 256 threads per block, 4 rows per block (64 threads = 1 KB row of float4s).
__global__ __launch_bounds__(256)
void gather_kernel(const float* __restrict__ src_feat,
                   const float* __restrict__ tgt_feat,
                   float* __restrict__ out) {
    int row = blockIdx.x * 4 + (threadIdx.x >> 6);   // 0 .. 2*MQ-1
    int col = threadIdx.x & 63;
    int side = (row >= MQ) ? 1 : 0;
    int q = side ? (row - MQ) : row;
    const float* f = side ? tgt_feat : src_feat;
    int idx = g_idx2[side][q];
    const float4* srcp = (const float4*)(f + (size_t)idx * CF);
    float4* dstp = (float4*)(out + (size_t)row * CF);
    dstp[col] = __ldg(&srcp[col]);
}

extern "C" void kernel_launch(void* const* d_in, const int* in_sizes, int n_in,
                              void* d_out, int out_size) {
    const float* src        = (const float*)d_in[0];   // [N, C]
    const float* tgt        = (const float*)d_in[1];   // [N, C]
    const float* src_coords = (const float*)d_in[2];   // [N, 3]
    const float* tgt_coords = (const float*)d_in[3];   // [N, 3]
    const float* src_sc     = (const float*)d_in[4];   // [M, 3]
    const float* tgt_sc     = (const float*)d_in[5];   // [M, 3]
    float* out = (float*)d_out;                        // [2*M, C]

    zero_kernel<<<(2 * G3 + 255) / 256, 256>>>();
    scatter_kernel<<<(2 * NPTS + 255) / 256, 256>>>(src_coords, tgt_coords);
    search1_kernel<<<(2 * MQ * 32 + 255) / 256, 256>>>(src_sc, tgt_sc);
    search2_kernel<<<2048, 256>>>(src_sc, tgt_sc);
    gather_kernel<<<2 * MQ / 4, 256>>>(src, tgt, out);
}

// round 13
// speedup vs baseline: 1.5433x; 1.2698x over previous
#include <cuda_runtime.h>
#include <cuda_bf16.h>
#include <cstdint>
#include <cfloat>

// Problem constants
#define NPTS 32768   // candidate points per side
#define MQ   8192    // query (shortcut) points per side
#define CF   256     // feature channels

// Grid constants
#define G     64
#define G3    (G * G * G)          // 262144 cells per side
#define HCELL 0.125f
#define INVH  8.0f
#define ORI   (-4.0f)
#define CAP   16                   // points per cell bin
#define OVMAX 4096                 // cell overflow list capacity per side
#define RBOX  2                    // phase-1 box radius (5x5x5 = 125 cells)

// Radius-band constants (phase 2)
#define NRB     64
#define RBWF    0.1f
#define INVRBW  10.0f
#define RCAP    2560               // points per radius bin
#define ROVMAX  2048               // radius spill capacity per side

// ---------------- scratch ----------------
__device__ int    g_cnt[2 * G3];                 // per-cell counts (2 MB)
__device__ float4 g_bin[2 * G3 * CAP];           // cell-binned points (134 MB)
__device__ int    g_ovn[2];                      // cell overflow counts
__device__ float4 g_ov[2][OVMAX];                // cell overflow points
__device__ int    g_rcnt[2][NRB];                // radius-bin counts
__device__ float4 g_rbin[2][NRB][RCAP];          // radius-binned points (5.2 MB)
__device__ int    g_rovn[2];                     // radius spill counts
__device__ float4 g_rov[2][ROVMAX];              // radius spill points
__device__ int    g_idx2[2][MQ];                 // 2nd-NN index per query
__device__ int    g_failn;                       // unresolved query count
__device__ int    g_fail[2 * MQ];                // unresolved (side<<16 | q)

// ---------------- helpers ----------------
__device__ __forceinline__ int cell_of(float v) {
    int c = (int)floorf((v - ORI) * INVH);
    return min(max(c, 0), G - 1);
}

__device__ __forceinline__ int rbin_of(float rho) {
    int b = (int)(rho * INVRBW);
    return min(b, NRB - 1);
}

struct Top2 {
    float d1, d2;
    int   i1, i2;
};

__device__ __forceinline__ void t2_ins(Top2& t, float d, int j) {
    bool a = d < t.d1;
    bool b = d < t.d2;
    t.i2 = a ? t.i1 : (b ? j : t.i2);
    t.d2 = a ? t.d1 : (b ? d : t.d2);
    t.i1 = a ? j : t.i1;
    t.d1 = a ? d : t.d1;
}

__device__ __forceinline__ void t2_merge(Top2& a, const Top2& b) {
    t2_ins(a, b.d1, b.i1);
    t2_ins(a, b.d2, b.i2);
}

__device__ __forceinline__ Top2 warp_merge(Top2 t) {
    #pragma unroll
    for (int off = 16; off; off >>= 1) {
        float od1 = __shfl_xor_sync(0xffffffffu, t.d1, off);
        int   oi1 = __shfl_xor_sync(0xffffffffu, t.i1, off);
        float od2 = __shfl_xor_sync(0xffffffffu, t.d2, off);
        int   oi2 = __shfl_xor_sync(0xffffffffu, t.i2, off);
        t2_ins(t, od1, oi1);
        t2_ins(t, od2, oi2);
    }
    return t;
}

// ---------------- K0: zero counts ----------------
__global__ void zero_kernel() {
    int gid = blockIdx.x * blockDim.x + threadIdx.x;
    if (gid < 2 * G3) g_cnt[gid] = 0;
    if (gid < 2 * NRB) ((int*)g_rcnt)[gid] = 0;
    if (gid < 2) { g_ovn[gid] = 0; g_rovn[gid] = 0; }
    if (gid == 0) g_failn = 0;
}

// ---------------- K1: scatter into cell bins + radius bins ----------------
// 512-thread blocks; radius-bin histogram aggregated in smem, one bulk
// global atomic per (block, bin) to kill counter contention.
__global__ __launch_bounds__(512)
void scatter_kernel(const float* __restrict__ src_coords,
                    const float* __restrict__ tgt_coords) {
    __shared__ int scnt[NRB];
    __shared__ int sbase[NRB];

    int u = blockIdx.x * 512 + threadIdx.x;          // 0 .. 2*NPTS-1
    int side = u >> 15;                              // constant per block
    int i = u & (NPTS - 1);
    const float* c = side ? tgt_coords : src_coords;
    float x = c[3 * i], y = c[3 * i + 1], z = c[3 * i + 2];
    float4 p = make_float4(x, y, z, __int_as_float(i));

    // cell bin (phase 1) — 262144 cells, negligible contention
    int cell = side * G3 + (cell_of(z) * G + cell_of(y)) * G + cell_of(x);
    int slot = atomicAdd(&g_cnt[cell], 1);
    if (slot < CAP) {
        g_bin[cell * CAP + slot] = p;
    } else {
        int o = atomicAdd(&g_ovn[side], 1);
        if (o < OVMAX) g_ov[side][o] = p;
    }

    // radius bin (phase 2) — smem aggregation
    if (threadIdx.x < NRB) scnt[threadIdx.x] = 0;
    __syncthreads();
    float rho = sqrtf(fmaf(x, x, fmaf(y, y, z * z)));
    int rb = rbin_of(rho);
    int myrank = atomicAdd(&scnt[rb], 1);
    __syncthreads();
    if (threadIdx.x < NRB) {
        int n = scnt[threadIdx.x];
        sbase[threadIdx.x] = n ? atomicAdd(&g_rcnt[side][threadIdx.x], n) : 0;
    }
    __syncthreads();
    int rs = sbase[rb] + myrank;
    if (rs < RCAP) {
        g_rbin[side][rb][rs] = p;
    } else {
        int o = atomicAdd(&g_rovn[side], 1);
        if (o < ROVMAX) g_rov[side][o] = p;
    }
}

// ---------------- K2: phase-1 warp-per-query, fixed r=2 box ----------------
__global__ __launch_bounds__(256)
void search1_kernel(const float* __restrict__ src_sc,
                    const float* __restrict__ tgt_sc) {
    int wid = (blockIdx.x * blockDim.x + threadIdx.x) >> 5;
    int lane = threadIdx.x & 31;
    if (wid >= 2 * MQ) return;
    int side = wid >> 13;
    int q = wid & (MQ - 1);
    const float* sc = side ? tgt_sc : src_sc;
    float qx = sc[3 * q], qy = sc[3 * q + 1], qz = sc[3 * q + 2];
    int cx = cell_of(qx), cy = cell_of(qy), cz = cell_of(qz);
    int sbase = side * G3;

    Top2 t;
    t.d1 = FLT_MAX; t.d2 = FLT_MAX; t.i1 = -1; t.i2 = -1;

    const int S = 2 * RBOX + 1;            // 5
    const int TOT = S * S * S;             // 125
    for (int c = lane; c < TOT; c += 32) {
        int dz = c / (S * S);
        int rem = c - dz * (S * S);
        int dy = rem / S;
        int dx = rem - dy * S;
        int x = cx + dx - RBOX, y = cy + dy - RBOX, z = cz + dz - RBOX;
        if ((unsigned)x >= G || (unsigned)y >= G || (unsigned)z >= G) continue;
        int cell = sbase + (z * G + y) * G + x;
        int n = min(g_cnt[cell], CAP);
        int base = cell * CAP;
        for (int k = 0; k < n; k++) {
            float4 p = g_bin[base + k];
            float ddx = qx - p.x, ddy = qy - p.y, ddz = qz - p.z;
            float d = fmaf(ddx, ddx, fmaf(ddy, ddy, ddz * ddz));
            t2_ins(t, d, __float_as_int(p.w));
        }
    }
    // cell overflow points (never duplicated in bins)
    int ovn = min(g_ovn[side], OVMAX);
    for (int o = lane; o < ovn; o += 32) {
        float4 p = g_ov[side][o];
        float ddx = qx - p.x, ddy = qy - p.y, ddz = qz - p.z;
        float d = fmaf(ddx, ddx, fmaf(ddy, ddy, ddz * ddz));
        t2_ins(t, d, __float_as_int(p.w));
    }

    Top2 m = warp_merge(t);
    const float bnd2 = (RBOX * HCELL) * (RBOX * HCELL);   // 0.0625
    if (m.d2 <= bnd2) {
        if (lane == 0) g_idx2[side][q] = m.i2;
    } else if (lane == 0) {
        int o = atomicAdd(&g_failn, 1);
        g_fail[o] = (side << 16) | q;
    }
}

// ---------------- K3: phase-2 doubling radial-window scan ----------------
// Block-per-item. Window [lo,hi] of radius bins; expand open edges by a
// doubling step each round; certify with reverse triangle inequality:
// dist(q,p) >= |rho_p - rho_q| >= (gap to window edge) for unscanned p.
__global__ __launch_bounds__(256)
void search2_kernel(const float* __restrict__ src_sc,
                    const float* __restrict__ tgt_sc) {
    __shared__ Top2 part[8];
    __shared__ float s_d2;
    __shared__ int   s_i2;
    __shared__ int   scnt_s[NRB];
    int tid = threadIdx.x;
    int warp = tid >> 5;
    int lane = tid & 31;
    int nf = g_failn;

    for (int item = blockIdx.x; item < nf; item += gridDim.x) {
        int packed = g_fail[item];
        int side = packed >> 16;
        int q = packed & 0xffff;
        const float* sc = side ? tgt_sc : src_sc;
        float qx = sc[3 * q], qy = sc[3 * q + 1], qz = sc[3 * q + 2];
        float rq = sqrtf(fmaf(qx, qx, fmaf(qy, qy, qz * qz)));

        // preload this side's bin counts into smem (one round trip)
        if (tid < NRB) scnt_s[tid] = min(g_rcnt[side][tid], RCAP);
        __syncthreads();

        Top2 t;
        t.d1 = FLT_MAX; t.d2 = FLT_MAX; t.i1 = -1; t.i2 = -1;

        // radius spill points (disjoint from radius bins)
        int rovn = min(g_rovn[side], ROVMAX);
        for (int o = tid; o < rovn; o += 256) {
            float4 p = g_rov[side][o];
            float ddx = qx - p.x, ddy = qy - p.y, ddz = qz - p.z;
            float d = fmaf(ddx, ddx, fmaf(ddy, ddy, ddz * ddz));
            t2_ins(t, d, __float_as_int(p.w));
        }

        int b0 = rbin_of(rq);
        // scan initial bin
        {
            int n = scnt_s[b0];
            const float4* bin = g_rbin[side][b0];
            for (int i = tid; i < n; i += 256) {
                float4 p = __ldg(&bin[i]);
                float ddx = qx - p.x, ddy = qy - p.y, ddz = qz - p.z;
                float d = fmaf(ddx, ddx, fmaf(ddy, ddy, ddz * ddz));
                t2_ins(t, d, __float_as_int(p.w));
            }
        }

        int lo = b0, hi = b0, step = 1;
        for (;;) {
            // two-level reduce: warp butterfly, then warp-0 butterfly over 8 partials
            Top2 w = warp_merge(t);
            if (lane == 0) part[warp] = w;
            __syncthreads();
            if (warp == 0) {
                Top2 m;
                if (lane < 8) m = part[lane];
                else { m.d1 = FLT_MAX; m.d2 = FLT_MAX; m.i1 = -1; m.i2 = -1; }
                m = warp_merge(m);
                if (lane == 0) { s_d2 = m.d2; s_i2 = m.i2; }
            }
            __syncthreads();
            float d2 = s_d2;

            float gapLo = rq - (float)lo * RBWF;          // to lower edge
            float gapHi = (float)(hi + 1) * RBWF - rq;    // to upper edge
            bool loOpen = (lo > 0) && (gapLo * gapLo < d2);
            bool hiOpen = (hi < NRB - 1) && (gapHi * gapHi < d2);
            if (!loOpen && !hiOpen) {
                if (tid == 0) g_idx2[side][q] = s_i2;
                break;
            }
            int nlo = loOpen ? max(lo - step, 0) : lo;
            int nhi = hiOpen ? min(hi + step, NRB - 1) : hi;

            for (int b = nlo; b < lo; b++) {
                int n = scnt_s[b];
                const float4* bin = g_rbin[side][b];
                for (int i = tid; i < n; i += 256) {
                    float4 p = __ldg(&bin[i]);
                    float ddx = qx - p.x, ddy = qy - p.y, ddz = qz - p.z;
                    float d = fmaf(ddx, ddx, fmaf(ddy, ddy, ddz * ddz));
                    t2_ins(t, d, __float_as_int(p.w));
                }
            }
            for (int b = hi + 1; b <= nhi; b++) {
                int n = scnt_s[b];
                const float4* bin = g_rbin[side][b];
                for (int i = tid; i < n; i += 256) {
                    float4 p = __ldg(&bin[i]);
                    float ddx = qx - p.x, ddy = qy - p.y, ddz = qz - p.z;
                    float d = fmaf(ddx, ddx, fmaf(ddy, ddy, ddz * ddz));
                    t2_ins(t, d, __float_as_int(p.w));
                }
            }
            lo = nlo; hi = nhi;
            step = min(step * 2, 16);
            __syncthreads();
        }
        __syncthreads();     // protect scnt_s reuse across items
    }
}

// ---------------- K4: gather features ----------------
// 256 threads per block, 4 rows per block (64 threads = 1 KB row of float4s).
__global__ __launch_bounds__(256)
void gather_kernel(const float* __restrict__ src_feat,
                   const float* __restrict__ tgt_feat,
                   float* __restrict__ out) {
    int row = blockIdx.x * 4 + (threadIdx.x >> 6);   // 0 .. 2*MQ-1
    int col = threadIdx.x & 63;
    int side = (row >= MQ) ? 1 : 0;
    int q = side ? (row - MQ) : row;
    const float* f = side ? tgt_feat : src_feat;
    int idx = g_idx2[side][q];
    const float4* srcp = (const float4*)(f + (size_t)idx * CF);
    float4* dstp = (float4*)(out + (size_t)row * CF);
    dstp[col] = __ldg(&srcp[col]);
}

extern "C" void kernel_launch(void* const* d_in, const int* in_sizes, int n_in,
                              void* d_out, int out_size) {
    const float* src        = (const float*)d_in[0];   // [N, C]
    const float* tgt        = (const float*)d_in[1];   // [N, C]
    const float* src_coords = (const float*)d_in[2];   // [N, 3]
    const float* tgt_coords = (const float*)d_in[3];   // [N, 3]
    const float* src_sc     = (const float*)d_in[4];   // [M, 3]
    const float* tgt_sc     = (const float*)d_in[5];   // [M, 3]
    float* out = (float*)d_out;                        // [2*M, C]

    zero_kernel<<<(2 * G3 + 255) / 256, 256>>>();
    scatter_kernel<<<2 * NPTS / 512, 512>>>(src_coords, tgt_coords);
    search1_kernel<<<(2 * MQ * 32 + 255) / 256, 256>>>(src_sc, tgt_sc);
    search2_kernel<<<2048, 256>>>(src_sc, tgt_sc);
    gather_kernel<<<2 * MQ / 4, 256>>>(src, tgt, out);
}